// round 15
// baseline (speedup 1.0000x reference)
#include <cuda_runtime.h>
#include <cuda_bf16.h>
#include <cuda_fp16.h>
#include <stdint.h>

#define NB   512
#define NL   64
#define NH   128
#define NENT 200000
#define NREL 500

// ---------------- scratch (__device__ globals; no allocs allowed) ----------
__device__ float g_Rproj[NREL * NH];
__device__ float g_vdW[NH];
__device__ float g_vdb[NH];
__device__ float g_q[NB * NH];
__device__ float g_cgate[NB * NH];
__device__ float g_bias[NB * NH];       // in_b + cond_in (vdb added in front)
__device__ __half g_Ph[NB * NH];
__device__ __half g_Eh[(size_t)NENT * NH];

// ---------------- shared macros ---------------------------------------------
#define MMA_F16(d, a, b) asm volatile( \
    "mma.sync.aligned.m16n8k16.row.col.f32.f16.f16.f32 " \
    "{%0,%1,%2,%3},{%4,%5,%6,%7},{%8,%9},{%0,%1,%2,%3};" \
    : "+f"(d[0]), "+f"(d[1]), "+f"(d[2]), "+f"(d[3]) \
    : "r"(a[0]), "r"(a[1]), "r"(a[2]), "r"(a[3]), "r"(b[0]), "r"(b[1]))

#define LDSM_X4(r, addr) asm volatile( \
    "ldmatrix.sync.aligned.m8n8.x4.shared.b16 {%0,%1,%2,%3}, [%4];" \
    : "=r"((r)[0]), "=r"((r)[1]), "=r"((r)[2]), "=r"((r)[3]) : "r"(addr))

#define LDSM_X4_T(r, addr) asm volatile( \
    "ldmatrix.sync.aligned.m8n8.x4.trans.shared.b16 {%0,%1,%2,%3}, [%4];" \
    : "=r"((r)[0]), "=r"((r)[1]), "=r"((r)[2]), "=r"((r)[3]) : "r"(addr))

#define CP_ASYNC16(dst, src, srcsz) asm volatile( \
    "cp.async.cg.shared.global [%0], [%1], 16, %2;" \
    :: "r"(dst), "l"(src), "r"(srcsz) : "memory")

__device__ __forceinline__ uint32_t smem_u32(const void* p) {
    return (uint32_t)__cvta_generic_to_shared(p);
}

__device__ __forceinline__ void f4_to_h2x2(float4 v, __half2* dst) {
    dst[0] = __floats2half2_rn(v.x, v.y);
    dst[1] = __floats2half2_rn(v.z, v.w);
}

// ---------------- setup: qcond (0..7) | prep (8..258), 2 CTAs/SM -----------
// qcond smem: sA 64x136 fp16 (17408) + sW 128x136 fp16 (34816) = 52224
#define SETUP_SMEM (64 * 136 * 2 + 128 * 136 * 2)
#define SETUP_GRID 259

__global__ __launch_bounds__(256, 2) void setup_kernel(
    const int* __restrict__ heads, const int* __restrict__ relations,
    const int* __restrict__ times, const float* __restrict__ entity_emb,
    const float* __restrict__ relation_emb, const float* __restrict__ time_emb,
    const float* __restrict__ query_W, const float* __restrict__ query_b,
    const float* __restrict__ in_W, const float* __restrict__ in_b,
    const float* __restrict__ delta_W, const float* __restrict__ delta_b,
    const float* __restrict__ hyper_in_W, const float* __restrict__ hyper_in_b,
    const float* __restrict__ hyper_gate_W, const float* __restrict__ hyper_gate_b)
{
    extern __shared__ char qsm[];
    int tid = threadIdx.x;
    int bid = blockIdx.x;

    if (bid >= 8) {
        // ---- prep: Rproj (2 rels/blk) or vdW/vdb ----
        int pb = bid - 8;
        int j = tid & 127;
        if (pb < 250) {
            float* sr = (float*)qsm;
            int half = tid >> 7;
            int r = pb * 2 + half;
            sr[half * NH + j] = relation_emb[r * NH + j];
            __syncthreads();
            float a0 = 0.f, a1 = 0.f;
            #pragma unroll 8
            for (int i = 0; i < NH; i += 2) {
                a0 += sr[half * NH + i]   * in_W[(NH + i) * NH + j];
                a1 += sr[half * NH + i+1] * in_W[(NH + i + 1) * NH + j];
            }
            g_Rproj[r * NH + j] = a0 + a1;
        } else {
            const float* v = (tid < 128) ? delta_W : delta_b;
            float a0 = 0.f, a1 = 0.f;
            #pragma unroll 8
            for (int t = 0; t < 128; t += 2) {
                a0 += v[t]   * in_W[(256 + t) * NH + j];
                a1 += v[t+1] * in_W[(256 + t + 1) * NH + j];
            }
            if (tid < 128) g_vdW[j] = a0 + a1; else g_vdb[j] = a0 + a1;
        }
        return;
    }

    // ---- qcond: q / cond_in / cond_gate for 64 batch rows ----
    // A processed in three 128-col chunks: c=0 head, c=1 rel, c=2 tf.
    __half* sA = (__half*)qsm;                        // 64 x 136
    __half* sW = (__half*)(qsm + 64 * 136 * 2);       // 128 x 136
    int warp = tid >> 5, lane = tid & 31;
    int b0 = bid * 64;

    int wm = (warp >> 2) * 32, wn = (warp & 3) * 32;
    int aRow = lane & 15, aCol = (lane >> 4) * 8;

    float qa[2][4][4];
    #pragma unroll
    for (int i = 0; i < 2; i++)
        #pragma unroll
        for (int j = 0; j < 4; j++)
            { qa[i][j][0]=0.f; qa[i][j][1]=0.f; qa[i][j][2]=0.f; qa[i][j][3]=0.f; }

    for (int c = 0; c < 3; c++) {
        // gather A chunk
        for (int l = warp; l < 64; l += 8) {
            int b = b0 + l;
            const float* src = (c == 0) ? entity_emb + (size_t)heads[b] * NH
                             : (c == 1) ? relation_emb + relations[b] * NH
                                        : time_emb + times[b] * NH;
            float4 v = ((const float4*)src)[lane];
            f4_to_h2x2(v, (__half2*)(sA + l * 136 + lane * 4));
        }
        // stage W chunk
        #pragma unroll
        for (int i = 0; i < 16; i++) {
            int idx = tid + i * 256;
            int k = idx >> 5, n = (idx & 31) * 4;
            float4 v = ((const float4*)(query_W + c * 128 * NH))[idx];
            f4_to_h2x2(v, (__half2*)(sW + k * 136 + n));
        }
        __syncthreads();
        #pragma unroll
        for (int ks = 0; ks < 8; ks++) {
            int kl = ks * 16;
            uint32_t aF[2][4], bF[2][4];
            #pragma unroll
            for (int mt = 0; mt < 2; mt++)
                LDSM_X4(aF[mt], smem_u32(sA + (wm + mt*16 + aRow) * 136 + kl + aCol));
            #pragma unroll
            for (int g = 0; g < 2; g++)
                LDSM_X4_T(bF[g], smem_u32(sW + (kl + aRow) * 136 + wn + g*16 + aCol));
            #pragma unroll
            for (int mt = 0; mt < 2; mt++)
                #pragma unroll
                for (int j = 0; j < 4; j++)
                    MMA_F16(qa[mt][j], aF[mt], (&bF[j >> 1][(j & 1) * 2]));
        }
        __syncthreads();
    }
    #pragma unroll
    for (int mt = 0; mt < 2; mt++) {
        int row = wm + mt * 16 + (lane >> 2);
        #pragma unroll
        for (int j = 0; j < 4; j++) {
            int col = wn + j * 8 + (lane & 3) * 2;
            g_q[(b0 + row) * NH + col]     = qa[mt][j][0] + query_b[col];
            g_q[(b0 + row) * NH + col + 1] = qa[mt][j][1] + query_b[col + 1];
            g_q[(b0 + row + 8) * NH + col]     = qa[mt][j][2] + query_b[col];
            g_q[(b0 + row + 8) * NH + col + 1] = qa[mt][j][3] + query_b[col + 1];
        }
    }

    // ---- cond: regather rel into sA, then two hyper passes ----
    for (int l = warp; l < 64; l += 8) {
        int b = b0 + l;
        float4 v = ((const float4*)(relation_emb + relations[b] * NH))[lane];
        f4_to_h2x2(v, (__half2*)(sA + l * 136 + lane * 4));
    }
    __syncthreads();

    float ci[2][4][4], cg[2][4][4];
    #pragma unroll
    for (int i = 0; i < 2; i++)
        #pragma unroll
        for (int j = 0; j < 4; j++) {
            ci[i][j][0]=0.f; ci[i][j][1]=0.f; ci[i][j][2]=0.f; ci[i][j][3]=0.f;
            cg[i][j][0]=0.f; cg[i][j][1]=0.f; cg[i][j][2]=0.f; cg[i][j][3]=0.f;
        }
    for (int pass = 0; pass < 2; pass++) {
        const float* W = pass ? hyper_gate_W : hyper_in_W;
        #pragma unroll
        for (int i = 0; i < 16; i++) {
            int idx = tid + i * 256;
            int k = idx >> 5, n = (idx & 31) * 4;
            float4 v = ((const float4*)W)[idx];
            f4_to_h2x2(v, (__half2*)(sW + k * 136 + n));
        }
        __syncthreads();
        #pragma unroll
        for (int ks = 0; ks < 8; ks++) {
            int kl = ks * 16;
            uint32_t aF[2][4], bF[2][4];
            #pragma unroll
            for (int mt = 0; mt < 2; mt++)
                LDSM_X4(aF[mt], smem_u32(sA + (wm + mt*16 + aRow) * 136 + kl + aCol));
            #pragma unroll
            for (int g = 0; g < 2; g++)
                LDSM_X4_T(bF[g], smem_u32(sW + (kl + aRow) * 136 + wn + g*16 + aCol));
            if (pass == 0) {
                #pragma unroll
                for (int mt = 0; mt < 2; mt++)
                    #pragma unroll
                    for (int j = 0; j < 4; j++)
                        MMA_F16(ci[mt][j], aF[mt], (&bF[j >> 1][(j & 1) * 2]));
            } else {
                #pragma unroll
                for (int mt = 0; mt < 2; mt++)
                    #pragma unroll
                    for (int j = 0; j < 4; j++)
                        MMA_F16(cg[mt][j], aF[mt], (&bF[j >> 1][(j & 1) * 2]));
            }
        }
        __syncthreads();
    }
    #pragma unroll
    for (int mt = 0; mt < 2; mt++) {
        int row = wm + mt * 16 + (lane >> 2);
        #pragma unroll
        for (int j = 0; j < 4; j++) {
            int col = wn + j * 8 + (lane & 3) * 2;
            #pragma unroll
            for (int h = 0; h < 2; h++) {
                int rr = b0 + row + h * 8;
                float i0 = ci[mt][j][h*2], i1 = ci[mt][j][h*2+1];
                float t0 = cg[mt][j][h*2], t1 = cg[mt][j][h*2+1];
                g_bias[rr * NH + col]     = in_b[col] + i0;
                g_bias[rr * NH + col + 1] = in_b[col+1] + i1;
                g_cgate[rr * NH + col]     = 1.f / (1.f + __expf(-(t0 + hyper_gate_b[col])));
                g_cgate[rr * NH + col + 1] = 1.f / (1.f + __expf(-(t1 + hyper_gate_b[col+1])));
            }
        }
    }
}

// ---------------- front + convertE, interleaved 1:3 in block order ---------
// bid % 4 == 0 -> front CTA (bid>>2), else convertE chunk.
#define F_LD 136
#define FRONT_SMEM 109056
#define NCONV_F4 (NENT * NH / 4)                      // 6,400,000
#define NCONV_BLK ((NCONV_F4 + 4095) / 4096)          // 1563
#define FRONT_GRID (2080 + 3)                         // 520 front slots + 1560+3 conv

__global__ __launch_bounds__(256, 2) void front_kernel(
    const int* __restrict__ relations,
    const int* __restrict__ hist_ent, const int* __restrict__ hist_rel,
    const float* __restrict__ hist_delta, const float* __restrict__ hist_mask,
    const float* __restrict__ entity_emb, const float* __restrict__ relation_emb,
    const float* __restrict__ in_W, const float* __restrict__ a_W,
    const float* __restrict__ a_b,
    const float* __restrict__ attn_W, const float* __restrict__ attn_b)
{
    extern __shared__ char fsm[];
    int tid = threadIdx.x;
    int bid = blockIdx.x;

    int b;
    if (bid >= 2080 || (bid & 3) != 0) {
        // ---- convertE chunk ----
        int cid = (bid >= 2080) ? 1560 + (bid - 2080)
                                : (bid >> 2) * 3 + (bid & 3) - 1;
        if (cid < NCONV_BLK) {
            int base = cid * 4096 + tid;
            #pragma unroll
            for (int i = 0; i < 16; i++) {
                int idx = base + i * 256;
                if (idx < NCONV_F4) {
                    float4 v = ((const float4*)entity_emb)[idx];
                    ((__half2*)g_Eh)[2*idx+0] = __floats2half2_rn(v.x, v.y);
                    ((__half2*)g_Eh)[2*idx+1] = __floats2half2_rn(v.z, v.w);
                }
            }
        }
        return;
    }
    b = bid >> 2;                     // 0..519
    if (b >= NB) return;

    float*  s_X   = (float*)fsm;
    __half* s_NEh = (__half*)(fsm + 32768);
    __half* s_NEl = (__half*)(fsm + 50176);
    float*  s_A   = (float*)(fsm + 32768);
    __half* s_W   = (__half*)(fsm + 67584);
    __half* s_Xh  = (__half*)(fsm + 84992);
    float*  s_misc = (float*)(fsm + 102400);
    float* s_rel    = s_misc;
    float* s_q      = s_misc + 128;
    float* s_cgate  = s_misc + 256;
    float* s_bias   = s_misc + 384;
    float* s_vdW    = s_misc + 512;
    float* s_attnW  = s_misc + 640;
    float* s_vdb    = s_misc + 896;
    float* s_scores = s_misc + 1152;
    float* s_attn   = s_misc + 1216;
    float* s_delta  = s_misc + 1280;
    float* s_mask   = s_misc + 1344;
    int*   s_hr     = (int*)(s_misc + 1408);
    float* s_qdot   = s_misc + 1472;
    float* s_ab     = s_misc + 1480;

    int warp = tid >> 5, lane = tid & 31;

    if (tid < 128) {
        s_rel[tid]   = relation_emb[relations[b] * NH + tid];
        s_q[tid]     = g_q[b * NH + tid];
        s_cgate[tid] = g_cgate[b * NH + tid];
        s_bias[tid]  = g_bias[b * NH + tid];
        s_vdW[tid]   = g_vdW[tid];
        s_vdb[tid]   = g_vdb[tid];
        s_ab[tid]    = a_b[tid];
    } else {
        int j = tid - 128;
        s_attnW[j]       = attn_W[j];
        s_attnW[128 + j] = attn_W[128 + j];
    }
    if (tid < 64) {
        s_delta[tid] = hist_delta[b * NL + tid];
        s_mask[tid]  = hist_mask[b * NL + tid];
        s_hr[tid]    = hist_rel[b * NL + tid];
    }

    for (int l = warp; l < NL; l += 8) {
        size_t e = (size_t)hist_ent[b * NL + l];
        float4 v = ((const float4*)(entity_emb + e * NH))[lane];
        __half2 h0 = __floats2half2_rn(v.x, v.y);
        __half2 h1 = __floats2half2_rn(v.z, v.w);
        __half2 l0 = __floats2half2_rn(v.x - __half2float(__low2half(h0)),
                                       v.y - __half2float(__high2half(h0)));
        __half2 l1 = __floats2half2_rn(v.z - __half2float(__low2half(h1)),
                                       v.w - __half2float(__high2half(h1)));
        ((__half2*)(s_NEh + l * F_LD))[lane * 2]     = h0;
        ((__half2*)(s_NEh + l * F_LD))[lane * 2 + 1] = h1;
        ((__half2*)(s_NEl + l * F_LD))[lane * 2]     = l0;
        ((__half2*)(s_NEl + l * F_LD))[lane * 2 + 1] = l1;
    }
    __syncthreads();

    int wm = (warp >> 2) * 32, wn = (warp & 3) * 32;
    int aRow = lane & 15, aCol = (lane >> 4) * 8;

    // GEMM1
    {
        float facc[2][4][4];
        #pragma unroll
        for (int i = 0; i < 2; i++)
            #pragma unroll
            for (int j = 0; j < 4; j++)
                { facc[i][j][0]=0.f; facc[i][j][1]=0.f; facc[i][j][2]=0.f; facc[i][j][3]=0.f; }
        for (int c = 0; c < 2; c++) {
            #pragma unroll
            for (int i = 0; i < 8; i++) {
                int idx = tid + i * 256;
                int k = idx >> 5, n = (idx & 31) * 4;
                float4 v = ((const float4*)in_W)[(c * 64 + k) * 32 + (idx & 31)];
                f4_to_h2x2(v, (__half2*)(s_W + k * F_LD + n));
            }
            __syncthreads();
            #pragma unroll
            for (int ks = 0; ks < 4; ks++) {
                int kg = c * 64 + ks * 16, kl = ks * 16;
                uint32_t aF[2][4], alF[2][4], bF[2][4];
                #pragma unroll
                for (int mt = 0; mt < 2; mt++) {
                    LDSM_X4(aF[mt],  smem_u32(s_NEh + (wm + mt*16 + aRow) * F_LD + kg + aCol));
                    LDSM_X4(alF[mt], smem_u32(s_NEl + (wm + mt*16 + aRow) * F_LD + kg + aCol));
                }
                #pragma unroll
                for (int g = 0; g < 2; g++)
                    LDSM_X4_T(bF[g], smem_u32(s_W + (kl + aRow) * F_LD + wn + g*16 + aCol));
                #pragma unroll
                for (int mt = 0; mt < 2; mt++)
                    #pragma unroll
                    for (int j = 0; j < 4; j++)
                        MMA_F16(facc[mt][j], aF[mt], (&bF[j >> 1][(j & 1) * 2]));
                #pragma unroll
                for (int mt = 0; mt < 2; mt++)
                    #pragma unroll
                    for (int j = 0; j < 4; j++)
                        MMA_F16(facc[mt][j], alF[mt], (&bF[j >> 1][(j & 1) * 2]));
            }
            __syncthreads();
        }
        #pragma unroll
        for (int mt = 0; mt < 2; mt++) {
            int row = wm + mt * 16 + (lane >> 2);
            #pragma unroll
            for (int j = 0; j < 4; j++) {
                int col = wn + j * 8 + (lane & 3) * 2;
                *(float2*)(s_X + row * NH + col) = make_float2(facc[mt][j][0], facc[mt][j][1]);
                *(float2*)(s_X + (row + 8) * NH + col) = make_float2(facc[mt][j][2], facc[mt][j][3]);
            }
        }
    }
    __syncthreads();

    // bias pass + Xh fp16
    {
        int r0 = (tid >> 4) * 4, c0 = (tid & 15) * 8;
        #pragma unroll
        for (int i = 0; i < 4; i++) {
            int l = r0 + i;
            float dl = s_delta[l];
            const float* rp = g_Rproj + s_hr[l] * NH + c0;
            #pragma unroll
            for (int j = 0; j < 8; j++) {
                float x = s_X[l * NH + c0 + j] + s_bias[c0 + j] + s_vdb[c0 + j]
                        + dl * s_vdW[c0 + j] + rp[j];
                s_X[l * NH + c0 + j] = x;
                s_Xh[l * F_LD + c0 + j] = __float2half_rn(x);
            }
        }
    }
    __syncthreads();

    // GEMM2
    {
        float facc[2][4][4];
        #pragma unroll
        for (int i = 0; i < 2; i++)
            #pragma unroll
            for (int j = 0; j < 4; j++)
                { facc[i][j][0]=0.f; facc[i][j][1]=0.f; facc[i][j][2]=0.f; facc[i][j][3]=0.f; }
        for (int c = 0; c < 2; c++) {
            #pragma unroll
            for (int i = 0; i < 8; i++) {
                int idx = tid + i * 256;
                int k = idx >> 5, n = (idx & 31) * 4;
                float4 v = ((const float4*)a_W)[(c * 64 + k) * 32 + (idx & 31)];
                f4_to_h2x2(v, (__half2*)(s_W + k * F_LD + n));
            }
            __syncthreads();
            #pragma unroll
            for (int ks = 0; ks < 4; ks++) {
                int kg = c * 64 + ks * 16, kl = ks * 16;
                uint32_t aF[2][4], bF[2][4];
                #pragma unroll
                for (int mt = 0; mt < 2; mt++)
                    LDSM_X4(aF[mt], smem_u32(s_Xh + (wm + mt*16 + aRow) * F_LD + kg + aCol));
                #pragma unroll
                for (int g = 0; g < 2; g++)
                    LDSM_X4_T(bF[g], smem_u32(s_W + (kl + aRow) * F_LD + wn + g*16 + aCol));
                #pragma unroll
                for (int mt = 0; mt < 2; mt++)
                    #pragma unroll
                    for (int j = 0; j < 4; j++)
                        MMA_F16(facc[mt][j], aF[mt], (&bF[j >> 1][(j & 1) * 2]));
            }
            __syncthreads();
        }
        #pragma unroll
        for (int mt = 0; mt < 2; mt++) {
            int row = wm + mt * 16 + (lane >> 2);
            #pragma unroll
            for (int j = 0; j < 4; j++) {
                int col = wn + j * 8 + (lane & 3) * 2;
                float v0 = 1.f / (1.f + __expf(-(facc[mt][j][0] + s_ab[col])));
                float v1 = 1.f / (1.f + __expf(-(facc[mt][j][1] + s_ab[col + 1])));
                float v2 = 1.f / (1.f + __expf(-(facc[mt][j][2] + s_ab[col])));
                float v3 = 1.f / (1.f + __expf(-(facc[mt][j][3] + s_ab[col + 1])));
                *(float2*)(s_A + row * NH + col) = make_float2(v0, v1);
                *(float2*)(s_A + (row + 8) * NH + col) = make_float2(v2, v3);
            }
        }
    }
    __syncthreads();

    // gated scan
    if (tid < 128) {
        float h = 0.f, cgt = s_cgate[tid];
        for (int l = 0; l < NL; l++) {
            float x = s_X[l * NH + tid];
            float a = s_A[l * NH + tid];
            float m = s_mask[l];
            float hn = a * h + (1.f - a) * x;
            h = m * hn + (1.f - m) * h;
            s_X[l * NH + tid] = h * cgt;
        }
    }
    __syncthreads();

    // attention
    if (tid < 32) {
        float p = 0.f;
        for (int j = tid; j < 128; j += 32) p += s_q[j] * s_attnW[128 + j];
        #pragma unroll
        for (int o = 16; o; o >>= 1) p += __shfl_xor_sync(~0u, p, o);
        if (tid == 0) s_qdot[0] = p + attn_b[0];
    }
    __syncthreads();
    for (int l = warp; l < NL; l += 8) {
        float p = 0.f;
        #pragma unroll
        for (int j = lane; j < 128; j += 32) p += s_X[l * NH + j] * s_attnW[j];
        #pragma unroll
        for (int o = 16; o; o >>= 1) p += __shfl_xor_sync(~0u, p, o);
        if (lane == 0) {
            float sc = tanhf(p + s_qdot[0]);
            s_scores[l] = (s_mask[l] <= 0.f) ? -1e9f : sc;
        }
    }
    __syncthreads();
    if (tid < 32) {
        float v0 = s_scores[tid], v1 = s_scores[tid + 32];
        float mx = fmaxf(v0, v1);
        #pragma unroll
        for (int o = 16; o; o >>= 1) mx = fmaxf(mx, __shfl_xor_sync(~0u, mx, o));
        float e0 = __expf(v0 - mx) * s_mask[tid];
        float e1 = __expf(v1 - mx) * s_mask[tid + 32];
        float s = e0 + e1;
        #pragma unroll
        for (int o = 16; o; o >>= 1) s += __shfl_xor_sync(~0u, s, o);
        s = fmaxf(s, 1e-9f);
        s_attn[tid] = e0 / s;
        s_attn[tid + 32] = e1 / s;
    }
    __syncthreads();
    if (tid < 128) {
        float c = 0.f;
        #pragma unroll 4
        for (int l = 0; l < NL; l++) c += s_X[l * NH + tid] * s_attn[l];
        float P = (s_q[tid] + c) * s_rel[tid];
        g_Ph[b * NH + tid] = __float2half_rn(P);
    }
}

// ---------------- score: fp16 GEMM, 128m x 128n, 2 CTAs/SM (proven) --------
#define ALD 136
#define SLD 72
#define SB_OFF 34816
#define BSTAGE 18432
#define NSTAGES 4
#define SCORE_SMEM (SB_OFF + NSTAGES * BSTAGE)   // 108544
#define NT128 ((NENT + 127) / 128)               // 1563
#define NSTRIDE 74

__global__ __launch_bounds__(256, 2) void score_kernel(float* __restrict__ out) {
    extern __shared__ char smem[];
    uint32_t sbase = smem_u32(smem);
    int tid = threadIdx.x, warp = tid >> 5, lane = tid & 31;
    int m0 = (blockIdx.x & 3) * 128;
    int nstart = blockIdx.x >> 2;

    int wm = (warp >> 2) * 64;
    int wn = (warp & 3) * 32;
    int aRow = lane & 15, aCol = (lane >> 4) * 8;
    int bRow = ((lane >> 4) << 3) + (lane & 7);
    int bCol = ((lane >> 3) & 1) * 8;
    int arow = lane >> 2, acol = (lane & 3) * 2;

    #pragma unroll
    for (int i = 0; i < 8; i++) {
        int idx = tid + i * 256;
        int r = idx >> 4, c = (idx & 15) * 8;
        *(uint4*)(smem + r * (ALD * 2) + c * 2) =
            *(const uint4*)(g_Ph + (size_t)(m0 + r) * NH + c);
    }

    int ntiles = 0;
    for (int t = nstart; t < NT128; t += NSTRIDE) ntiles++;
    int steps = ntiles * 2;
    if (steps == 0) return;

    auto fillB = [&](int s) {
        int stage = s & 3;
        int n0 = (nstart + (s >> 1) * NSTRIDE) * 128;
        int kc = (s & 1) * 64;
        uint32_t bh = sbase + SB_OFF + stage * BSTAGE;
        #pragma unroll
        for (int i = 0; i < 4; i++) {
            int idx = tid + i * 256;
            int r = idx >> 3, c = (idx & 7) * 8;
            int er = n0 + r;
            uint32_t srcsz = (er < NENT) ? 16u : 0u;
            size_t go = (size_t)er * NH + kc + c;
            uint32_t so = (uint32_t)(r * (SLD * 2) + c * 2);
            CP_ASYNC16(bh + so, g_Eh + (srcsz ? go : 0), srcsz);
        }
    };

    fillB(0); asm volatile("cp.async.commit_group;" ::: "memory");
    if (steps > 1) { fillB(1); asm volatile("cp.async.commit_group;" ::: "memory"); }
    if (steps > 2) { fillB(2); asm volatile("cp.async.commit_group;" ::: "memory"); }

    float acc[4][4][4];
    #pragma unroll
    for (int i = 0; i < 4; i++)
        #pragma unroll
        for (int j = 0; j < 4; j++)
            { acc[i][j][0]=0.f; acc[i][j][1]=0.f; acc[i][j][2]=0.f; acc[i][j][3]=0.f; }

    for (int s = 0; s < steps; s++) {
        int rem = steps - 1 - s;
        if (rem >= 2)      asm volatile("cp.async.wait_group 2;" ::: "memory");
        else if (rem == 1) asm volatile("cp.async.wait_group 1;" ::: "memory");
        else               asm volatile("cp.async.wait_group 0;" ::: "memory");
        __syncthreads();

        if (s + 3 < steps) {
            fillB(s + 3);
            asm volatile("cp.async.commit_group;" ::: "memory");
        }

        int stage = s & 3;
        int kA = (s & 1) * 64;
        const char* bhp = smem + SB_OFF + stage * BSTAGE;

        #pragma unroll
        for (int ks = 0; ks < 4; ks++) {
            int k = ks * 16;
            uint32_t aH[4][4], bH[2][4];
            #pragma unroll
            for (int mt = 0; mt < 4; mt++)
                LDSM_X4(aH[mt], sbase +
                        (wm + mt * 16 + aRow) * (ALD * 2) + (kA + k + aCol) * 2);
            #pragma unroll
            for (int p = 0; p < 2; p++)
                LDSM_X4(bH[p], smem_u32(bhp + (wn + p * 16 + bRow) * (SLD * 2) + (k + bCol) * 2));
            #pragma unroll
            for (int mt = 0; mt < 4; mt++)
                #pragma unroll
                for (int nt = 0; nt < 4; nt++)
                    MMA_F16(acc[mt][nt], aH[mt], (&bH[nt >> 1][(nt & 1) * 2]));
        }

        if (s & 1) {
            int n0 = (nstart + (s >> 1) * NSTRIDE) * 128;
            #pragma unroll
            for (int mt = 0; mt < 4; mt++) {
                int row = m0 + wm + mt * 16 + arow;
                #pragma unroll
                for (int nt = 0; nt < 4; nt++) {
                    int col = n0 + wn + nt * 8 + acol;
                    if (col < NENT) {
                        __stcs((float2*)(out + (size_t)row * NENT + col),
                               make_float2(acc[mt][nt][0], acc[mt][nt][1]));
                        __stcs((float2*)(out + (size_t)(row + 8) * NENT + col),
                               make_float2(acc[mt][nt][2], acc[mt][nt][3]));
                    }
                }
            }
            #pragma unroll
            for (int i = 0; i < 4; i++)
                #pragma unroll
                for (int j = 0; j < 4; j++)
                    { acc[i][j][0]=0.f; acc[i][j][1]=0.f; acc[i][j][2]=0.f; acc[i][j][3]=0.f; }
        }
    }
}

// ---------------- launch ----------------------------------------------------
extern "C" void kernel_launch(void* const* d_in, const int* in_sizes, int n_in,
                              void* d_out, int out_size) {
    const int*   heads        = (const int*)d_in[0];
    const int*   relations    = (const int*)d_in[1];
    const int*   times        = (const int*)d_in[2];
    const int*   hist_ent     = (const int*)d_in[3];
    const int*   hist_rel     = (const int*)d_in[4];
    const float* hist_delta   = (const float*)d_in[5];
    const float* hist_mask    = (const float*)d_in[6];
    const float* entity_emb   = (const float*)d_in[7];
    const float* relation_emb = (const float*)d_in[8];
    const float* time_emb     = (const float*)d_in[9];
    const float* delta_W      = (const float*)d_in[10];
    const float* delta_b      = (const float*)d_in[11];
    const float* query_W      = (const float*)d_in[12];
    const float* query_b      = (const float*)d_in[13];
    const float* in_W         = (const float*)d_in[14];
    const float* in_b         = (const float*)d_in[15];
    const float* a_W          = (const float*)d_in[16];
    const float* a_b          = (const float*)d_in[17];
    const float* hyper_in_W   = (const float*)d_in[18];
    const float* hyper_in_b   = (const float*)d_in[19];
    const float* hyper_gate_W = (const float*)d_in[20];
    const float* hyper_gate_b = (const float*)d_in[21];
    const float* attn_W       = (const float*)d_in[22];
    const float* attn_b       = (const float*)d_in[23];
    float* out = (float*)d_out;

    cudaFuncSetAttribute(setup_kernel, cudaFuncAttributeMaxDynamicSharedMemorySize, SETUP_SMEM);
    cudaFuncSetAttribute(front_kernel, cudaFuncAttributeMaxDynamicSharedMemorySize, FRONT_SMEM);
    cudaFuncSetAttribute(score_kernel, cudaFuncAttributeMaxDynamicSharedMemorySize, SCORE_SMEM);

    setup_kernel<<<SETUP_GRID, 256, SETUP_SMEM>>>(
        heads, relations, times, entity_emb, relation_emb, time_emb,
        query_W, query_b, in_W, in_b, delta_W, delta_b,
        hyper_in_W, hyper_in_b, hyper_gate_W, hyper_gate_b);
    front_kernel<<<FRONT_GRID, 256, FRONT_SMEM>>>(
        relations, hist_ent, hist_rel, hist_delta, hist_mask,
        entity_emb, relation_emb, in_W, a_W, a_b, attn_W, attn_b);
    score_kernel<<<296, 256, SCORE_SMEM>>>(out);
}

// round 16
// speedup vs baseline: 1.0297x; 1.0297x over previous
#include <cuda_runtime.h>
#include <cuda_bf16.h>
#include <cuda_fp16.h>
#include <stdint.h>

#define NB   512
#define NL   64
#define NH   128
#define NENT 200000
#define NREL 500

// ---------------- scratch (__device__ globals; no allocs allowed) ----------
__device__ float g_Rproj[NREL * NH];
__device__ float g_vdW[NH];
__device__ float g_vdb[NH];
__device__ float g_q[NB * NH];
__device__ float g_cgate[NB * NH];
__device__ float g_bias[NB * NH];       // in_b + cond_in (vdb added in front)
__device__ __half g_Ph[NB * NH];
__device__ __half g_Eh[(size_t)NENT * NH];
__device__ int g_cnt[4];                // per-m-quadrant front completion count

// ---------------- shared macros ---------------------------------------------
#define MMA_F16(d, a, b) asm volatile( \
    "mma.sync.aligned.m16n8k16.row.col.f32.f16.f16.f32 " \
    "{%0,%1,%2,%3},{%4,%5,%6,%7},{%8,%9},{%0,%1,%2,%3};" \
    : "+f"(d[0]), "+f"(d[1]), "+f"(d[2]), "+f"(d[3]) \
    : "r"(a[0]), "r"(a[1]), "r"(a[2]), "r"(a[3]), "r"(b[0]), "r"(b[1]))

#define LDSM_X4(r, addr) asm volatile( \
    "ldmatrix.sync.aligned.m8n8.x4.shared.b16 {%0,%1,%2,%3}, [%4];" \
    : "=r"((r)[0]), "=r"((r)[1]), "=r"((r)[2]), "=r"((r)[3]) : "r"(addr))

#define LDSM_X4_T(r, addr) asm volatile( \
    "ldmatrix.sync.aligned.m8n8.x4.trans.shared.b16 {%0,%1,%2,%3}, [%4];" \
    : "=r"((r)[0]), "=r"((r)[1]), "=r"((r)[2]), "=r"((r)[3]) : "r"(addr))

#define CP_ASYNC16(dst, src, srcsz) asm volatile( \
    "cp.async.cg.shared.global [%0], [%1], 16, %2;" \
    :: "r"(dst), "l"(src), "r"(srcsz) : "memory")

__device__ __forceinline__ uint32_t smem_u32(const void* p) {
    return (uint32_t)__cvta_generic_to_shared(p);
}

__device__ __forceinline__ void f4_to_h2x2(float4 v, __half2* dst) {
    dst[0] = __floats2half2_rn(v.x, v.y);
    dst[1] = __floats2half2_rn(v.z, v.w);
}

// ---------------- setup: qcond (0..7) | prep (8..258) | convertE (259..) ----
#define Q_LD 392
#define SETUP_SMEM (64 * Q_LD * 2 + 128 * 136 * 2)   // 84992
#define NCONV_F4 (NENT * NH / 4)                      // 6,400,000
#define NCONV_BLK ((NCONV_F4 + 4095) / 4096)          // 1563
#define SETUP_GRID (8 + 251 + NCONV_BLK)

__global__ __launch_bounds__(256) void setup_kernel(
    const int* __restrict__ heads, const int* __restrict__ relations,
    const int* __restrict__ times, const float* __restrict__ entity_emb,
    const float* __restrict__ relation_emb, const float* __restrict__ time_emb,
    const float* __restrict__ query_W, const float* __restrict__ query_b,
    const float* __restrict__ in_W, const float* __restrict__ in_b,
    const float* __restrict__ delta_W, const float* __restrict__ delta_b,
    const float* __restrict__ hyper_in_W, const float* __restrict__ hyper_in_b,
    const float* __restrict__ hyper_gate_W, const float* __restrict__ hyper_gate_b)
{
    extern __shared__ char qsm[];
    int tid = threadIdx.x;
    int bid = blockIdx.x;

    if (bid >= 259) {
        // ---- convertE: fp32 E -> fp16 g_Eh ----
        int base = (bid - 259) * 4096 + tid;
        #pragma unroll
        for (int i = 0; i < 16; i++) {
            int idx = base + i * 256;
            if (idx < NCONV_F4) {
                float4 v = ((const float4*)entity_emb)[idx];
                ((__half2*)g_Eh)[2*idx+0] = __floats2half2_rn(v.x, v.y);
                ((__half2*)g_Eh)[2*idx+1] = __floats2half2_rn(v.z, v.w);
            }
        }
        return;
    }

    if (bid >= 8) {
        // ---- prep: Rproj (2 rels/blk) or vdW/vdb ----
        int pb = bid - 8;
        int j = tid & 127;
        if (pb < 250) {
            float* sr = (float*)qsm;
            int half = tid >> 7;
            int r = pb * 2 + half;
            sr[half * NH + j] = relation_emb[r * NH + j];
            __syncthreads();
            float a0 = 0.f, a1 = 0.f;
            #pragma unroll 8
            for (int i = 0; i < NH; i += 2) {
                a0 += sr[half * NH + i]   * in_W[(NH + i) * NH + j];
                a1 += sr[half * NH + i+1] * in_W[(NH + i + 1) * NH + j];
            }
            g_Rproj[r * NH + j] = a0 + a1;
        } else {
            const float* v = (tid < 128) ? delta_W : delta_b;
            float a0 = 0.f, a1 = 0.f;
            #pragma unroll 8
            for (int t = 0; t < 128; t += 2) {
                a0 += v[t]   * in_W[(256 + t) * NH + j];
                a1 += v[t+1] * in_W[(256 + t + 1) * NH + j];
            }
            if (tid < 128) g_vdW[j] = a0 + a1; else g_vdb[j] = a0 + a1;
        }
        return;
    }

    // ---- qcond: q / cond_in / cond_gate for 64 batch rows ----
    if (bid == 0 && tid < 4) g_cnt[tid] = 0;          // reset handshake counters
    __half* sA = (__half*)qsm;
    __half* sW = (__half*)(qsm + 64 * Q_LD * 2);
    int warp = tid >> 5, lane = tid & 31;
    int b0 = bid * 64;

    for (int l = warp; l < 64; l += 8) {
        int b = b0 + l;
        float4 v0 = ((const float4*)(entity_emb + (size_t)heads[b] * NH))[lane];
        float4 v1 = ((const float4*)(relation_emb + relations[b] * NH))[lane];
        float4 v2 = ((const float4*)(time_emb + times[b] * NH))[lane];
        f4_to_h2x2(v0, (__half2*)(sA + l * Q_LD + lane * 4));
        f4_to_h2x2(v1, (__half2*)(sA + l * Q_LD + 128 + lane * 4));
        f4_to_h2x2(v2, (__half2*)(sA + l * Q_LD + 256 + lane * 4));
    }
    __syncthreads();

    int wm = (warp >> 2) * 32, wn = (warp & 3) * 32;
    int aRow = lane & 15, aCol = (lane >> 4) * 8;

    float qa[2][4][4];
    #pragma unroll
    for (int i = 0; i < 2; i++)
        #pragma unroll
        for (int j = 0; j < 4; j++)
            { qa[i][j][0]=0.f; qa[i][j][1]=0.f; qa[i][j][2]=0.f; qa[i][j][3]=0.f; }
    for (int c = 0; c < 3; c++) {
        #pragma unroll
        for (int i = 0; i < 16; i++) {
            int idx = tid + i * 256;
            int k = idx >> 5, n = (idx & 31) * 4;
            float4 v = ((const float4*)(query_W + c * 128 * NH))[idx];
            f4_to_h2x2(v, (__half2*)(sW + k * 136 + n));
        }
        __syncthreads();
        #pragma unroll
        for (int ks = 0; ks < 8; ks++) {
            int kg = c * 128 + ks * 16, kl = ks * 16;
            uint32_t aF[2][4], bF[2][4];
            #pragma unroll
            for (int mt = 0; mt < 2; mt++)
                LDSM_X4(aF[mt], smem_u32(sA + (wm + mt*16 + aRow) * Q_LD + kg + aCol));
            #pragma unroll
            for (int g = 0; g < 2; g++)
                LDSM_X4_T(bF[g], smem_u32(sW + (kl + aRow) * 136 + wn + g*16 + aCol));
            #pragma unroll
            for (int mt = 0; mt < 2; mt++)
                #pragma unroll
                for (int j = 0; j < 4; j++)
                    MMA_F16(qa[mt][j], aF[mt], (&bF[j >> 1][(j & 1) * 2]));
        }
        __syncthreads();
    }
    #pragma unroll
    for (int mt = 0; mt < 2; mt++) {
        int row = wm + mt * 16 + (lane >> 2);
        #pragma unroll
        for (int j = 0; j < 4; j++) {
            int col = wn + j * 8 + (lane & 3) * 2;
            g_q[(b0 + row) * NH + col]     = qa[mt][j][0] + query_b[col];
            g_q[(b0 + row) * NH + col + 1] = qa[mt][j][1] + query_b[col + 1];
            g_q[(b0 + row + 8) * NH + col]     = qa[mt][j][2] + query_b[col];
            g_q[(b0 + row + 8) * NH + col + 1] = qa[mt][j][3] + query_b[col + 1];
        }
    }

    float ci[2][4][4], cg[2][4][4];
    #pragma unroll
    for (int i = 0; i < 2; i++)
        #pragma unroll
        for (int j = 0; j < 4; j++) {
            ci[i][j][0]=0.f; ci[i][j][1]=0.f; ci[i][j][2]=0.f; ci[i][j][3]=0.f;
            cg[i][j][0]=0.f; cg[i][j][1]=0.f; cg[i][j][2]=0.f; cg[i][j][3]=0.f;
        }
    for (int pass = 0; pass < 2; pass++) {
        const float* W = pass ? hyper_gate_W : hyper_in_W;
        #pragma unroll
        for (int i = 0; i < 16; i++) {
            int idx = tid + i * 256;
            int k = idx >> 5, n = (idx & 31) * 4;
            float4 v = ((const float4*)W)[idx];
            f4_to_h2x2(v, (__half2*)(sW + k * 136 + n));
        }
        __syncthreads();
        #pragma unroll
        for (int ks = 0; ks < 8; ks++) {
            int kl = ks * 16;
            uint32_t aF[2][4], bF[2][4];
            #pragma unroll
            for (int mt = 0; mt < 2; mt++)
                LDSM_X4(aF[mt], smem_u32(sA + (wm + mt*16 + aRow) * Q_LD + 128 + kl + aCol));
            #pragma unroll
            for (int g = 0; g < 2; g++)
                LDSM_X4_T(bF[g], smem_u32(sW + (kl + aRow) * 136 + wn + g*16 + aCol));
            if (pass == 0) {
                #pragma unroll
                for (int mt = 0; mt < 2; mt++)
                    #pragma unroll
                    for (int j = 0; j < 4; j++)
                        MMA_F16(ci[mt][j], aF[mt], (&bF[j >> 1][(j & 1) * 2]));
            } else {
                #pragma unroll
                for (int mt = 0; mt < 2; mt++)
                    #pragma unroll
                    for (int j = 0; j < 4; j++)
                        MMA_F16(cg[mt][j], aF[mt], (&bF[j >> 1][(j & 1) * 2]));
            }
        }
        __syncthreads();
    }
    #pragma unroll
    for (int mt = 0; mt < 2; mt++) {
        int row = wm + mt * 16 + (lane >> 2);
        #pragma unroll
        for (int j = 0; j < 4; j++) {
            int col = wn + j * 8 + (lane & 3) * 2;
            #pragma unroll
            for (int h = 0; h < 2; h++) {
                int rr = b0 + row + h * 8;
                float i0 = ci[mt][j][h*2], i1 = ci[mt][j][h*2+1];
                float t0 = cg[mt][j][h*2], t1 = cg[mt][j][h*2+1];
                g_bias[rr * NH + col]     = in_b[col] + i0;
                g_bias[rr * NH + col + 1] = in_b[col+1] + i1;
                g_cgate[rr * NH + col]     = 1.f / (1.f + __expf(-(t0 + hyper_gate_b[col])));
                g_cgate[rr * NH + col + 1] = 1.f / (1.f + __expf(-(t1 + hyper_gate_b[col+1])));
            }
        }
    }
}

// ---------------- fused main: front (0..511) + score (512..807) ------------
#define F_LD 136
#define MAIN_SMEM 109056
// score layout constants (within the same dynamic smem)
#define ALD 136
#define SLD 72
#define SB_OFF 34816
#define BSTAGE 18432
#define NT128 ((NENT + 127) / 128)               // 1563
#define NSTRIDE 74
#define MAIN_GRID (NB + 296)

__global__ __launch_bounds__(256, 2) void main_kernel(
    const int* __restrict__ relations,
    const int* __restrict__ hist_ent, const int* __restrict__ hist_rel,
    const float* __restrict__ hist_delta, const float* __restrict__ hist_mask,
    const float* __restrict__ entity_emb, const float* __restrict__ relation_emb,
    const float* __restrict__ in_W, const float* __restrict__ a_W,
    const float* __restrict__ a_b,
    const float* __restrict__ attn_W, const float* __restrict__ attn_b,
    float* __restrict__ out)
{
    extern __shared__ char fsm[];
    int tid = threadIdx.x;
    int warp = tid >> 5, lane = tid & 31;

    if (blockIdx.x >= NB) {
        // ================= SCORE path =================
        uint32_t sbase = smem_u32(fsm);
        int sbid = blockIdx.x - NB;
        int m0 = (sbid & 3) * 128;
        int nstart = sbid >> 2;

        int wm = (warp >> 2) * 64;
        int wn = (warp & 3) * 32;
        int aRow = lane & 15, aCol = (lane >> 4) * 8;
        int bRow = ((lane >> 4) << 3) + (lane & 7);
        int bCol = ((lane >> 3) & 1) * 8;
        int arow = lane >> 2, acol = (lane & 3) * 2;

        int ntiles = 0;
        for (int t = nstart; t < NT128; t += NSTRIDE) ntiles++;
        int steps = ntiles * 2;
        if (steps == 0) return;

        auto fillB = [&](int s) {
            int stage = s & 3;
            int n0 = (nstart + (s >> 1) * NSTRIDE) * 128;
            int kc = (s & 1) * 64;
            uint32_t bh = sbase + SB_OFF + stage * BSTAGE;
            #pragma unroll
            for (int i = 0; i < 4; i++) {
                int idx = tid + i * 256;
                int r = idx >> 3, c = (idx & 7) * 8;
                int er = n0 + r;
                uint32_t srcsz = (er < NENT) ? 16u : 0u;
                size_t go = (size_t)er * NH + kc + c;
                uint32_t so = (uint32_t)(r * (SLD * 2) + c * 2);
                CP_ASYNC16(bh + so, g_Eh + (srcsz ? go : 0), srcsz);
            }
        };

        // B prefetch first — independent of front output
        fillB(0); asm volatile("cp.async.commit_group;" ::: "memory");
        if (steps > 1) { fillB(1); asm volatile("cp.async.commit_group;" ::: "memory"); }
        if (steps > 2) { fillB(2); asm volatile("cp.async.commit_group;" ::: "memory"); }

        // wait for front blocks of this m-quadrant
        if (tid == 0) {
            volatile int* c = &g_cnt[m0 >> 7];
            while (*c < 128) { }
        }
        __syncthreads();

        // A resident fill
        #pragma unroll
        for (int i = 0; i < 8; i++) {
            int idx = tid + i * 256;
            int r = idx >> 4, c = (idx & 15) * 8;
            *(uint4*)(fsm + r * (ALD * 2) + c * 2) =
                *(const uint4*)(g_Ph + (size_t)(m0 + r) * NH + c);
        }

        float acc[4][4][4];
        #pragma unroll
        for (int i = 0; i < 4; i++)
            #pragma unroll
            for (int j = 0; j < 4; j++)
                { acc[i][j][0]=0.f; acc[i][j][1]=0.f; acc[i][j][2]=0.f; acc[i][j][3]=0.f; }

        for (int s = 0; s < steps; s++) {
            int rem = steps - 1 - s;
            if (rem >= 2)      asm volatile("cp.async.wait_group 2;" ::: "memory");
            else if (rem == 1) asm volatile("cp.async.wait_group 1;" ::: "memory");
            else               asm volatile("cp.async.wait_group 0;" ::: "memory");
            __syncthreads();

            if (s + 3 < steps) {
                fillB(s + 3);
                asm volatile("cp.async.commit_group;" ::: "memory");
            }

            int stage = s & 3;
            int kA = (s & 1) * 64;
            const char* bhp = fsm + SB_OFF + stage * BSTAGE;

            #pragma unroll
            for (int ks = 0; ks < 4; ks++) {
                int k = ks * 16;
                uint32_t aH[4][4], bH[2][4];
                #pragma unroll
                for (int mt = 0; mt < 4; mt++)
                    LDSM_X4(aH[mt], sbase +
                            (wm + mt * 16 + aRow) * (ALD * 2) + (kA + k + aCol) * 2);
                #pragma unroll
                for (int p = 0; p < 2; p++)
                    LDSM_X4(bH[p], smem_u32(bhp + (wn + p * 16 + bRow) * (SLD * 2) + (k + bCol) * 2));
                #pragma unroll
                for (int mt = 0; mt < 4; mt++)
                    #pragma unroll
                    for (int nt = 0; nt < 4; nt++)
                        MMA_F16(acc[mt][nt], aH[mt], (&bH[nt >> 1][(nt & 1) * 2]));
            }

            if (s & 1) {
                int n0 = (nstart + (s >> 1) * NSTRIDE) * 128;
                #pragma unroll
                for (int mt = 0; mt < 4; mt++) {
                    int row = m0 + wm + mt * 16 + arow;
                    #pragma unroll
                    for (int nt = 0; nt < 4; nt++) {
                        int col = n0 + wn + nt * 8 + acol;
                        if (col < NENT) {
                            __stcs((float2*)(out + (size_t)row * NENT + col),
                                   make_float2(acc[mt][nt][0], acc[mt][nt][1]));
                            __stcs((float2*)(out + (size_t)(row + 8) * NENT + col),
                                   make_float2(acc[mt][nt][2], acc[mt][nt][3]));
                        }
                    }
                }
                #pragma unroll
                for (int i = 0; i < 4; i++)
                    #pragma unroll
                    for (int j = 0; j < 4; j++)
                        { acc[i][j][0]=0.f; acc[i][j][1]=0.f; acc[i][j][2]=0.f; acc[i][j][3]=0.f; }
            }
        }
        return;
    }

    // ================= FRONT path =================
    int b = blockIdx.x;

    float*  s_X   = (float*)fsm;
    __half* s_NEh = (__half*)(fsm + 32768);
    __half* s_NEl = (__half*)(fsm + 50176);
    float*  s_A   = (float*)(fsm + 32768);
    __half* s_W   = (__half*)(fsm + 67584);
    __half* s_Xh  = (__half*)(fsm + 84992);
    float*  s_misc = (float*)(fsm + 102400);
    float* s_rel    = s_misc;
    float* s_q      = s_misc + 128;
    float* s_cgate  = s_misc + 256;
    float* s_bias   = s_misc + 384;
    float* s_vdW    = s_misc + 512;
    float* s_attnW  = s_misc + 640;
    float* s_vdb    = s_misc + 896;
    float* s_scores = s_misc + 1152;
    float* s_attn   = s_misc + 1216;
    float* s_delta  = s_misc + 1280;
    float* s_mask   = s_misc + 1344;
    int*   s_hr     = (int*)(s_misc + 1408);
    float* s_qdot   = s_misc + 1472;
    float* s_ab     = s_misc + 1480;

    if (tid < 128) {
        s_rel[tid]   = relation_emb[relations[b] * NH + tid];
        s_q[tid]     = g_q[b * NH + tid];
        s_cgate[tid] = g_cgate[b * NH + tid];
        s_bias[tid]  = g_bias[b * NH + tid];
        s_vdW[tid]   = g_vdW[tid];
        s_vdb[tid]   = g_vdb[tid];
        s_ab[tid]    = a_b[tid];
    } else {
        int j = tid - 128;
        s_attnW[j]       = attn_W[j];
        s_attnW[128 + j] = attn_W[128 + j];
    }
    if (tid < 64) {
        s_delta[tid] = hist_delta[b * NL + tid];
        s_mask[tid]  = hist_mask[b * NL + tid];
        s_hr[tid]    = hist_rel[b * NL + tid];
    }

    for (int l = warp; l < NL; l += 8) {
        size_t e = (size_t)hist_ent[b * NL + l];
        float4 v = ((const float4*)(entity_emb + e * NH))[lane];
        __half2 h0 = __floats2half2_rn(v.x, v.y);
        __half2 h1 = __floats2half2_rn(v.z, v.w);
        __half2 l0 = __floats2half2_rn(v.x - __half2float(__low2half(h0)),
                                       v.y - __half2float(__high2half(h0)));
        __half2 l1 = __floats2half2_rn(v.z - __half2float(__low2half(h1)),
                                       v.w - __half2float(__high2half(h1)));
        ((__half2*)(s_NEh + l * F_LD))[lane * 2]     = h0;
        ((__half2*)(s_NEh + l * F_LD))[lane * 2 + 1] = h1;
        ((__half2*)(s_NEl + l * F_LD))[lane * 2]     = l0;
        ((__half2*)(s_NEl + l * F_LD))[lane * 2 + 1] = l1;
    }
    __syncthreads();

    int wm = (warp >> 2) * 32, wn = (warp & 3) * 32;
    int aRow = lane & 15, aCol = (lane >> 4) * 8;

    // GEMM1
    {
        float facc[2][4][4];
        #pragma unroll
        for (int i = 0; i < 2; i++)
            #pragma unroll
            for (int j = 0; j < 4; j++)
                { facc[i][j][0]=0.f; facc[i][j][1]=0.f; facc[i][j][2]=0.f; facc[i][j][3]=0.f; }
        for (int c = 0; c < 2; c++) {
            #pragma unroll
            for (int i = 0; i < 8; i++) {
                int idx = tid + i * 256;
                int k = idx >> 5, n = (idx & 31) * 4;
                float4 v = ((const float4*)in_W)[(c * 64 + k) * 32 + (idx & 31)];
                f4_to_h2x2(v, (__half2*)(s_W + k * F_LD + n));
            }
            __syncthreads();
            #pragma unroll
            for (int ks = 0; ks < 4; ks++) {
                int kg = c * 64 + ks * 16, kl = ks * 16;
                uint32_t aF[2][4], alF[2][4], bF[2][4];
                #pragma unroll
                for (int mt = 0; mt < 2; mt++) {
                    LDSM_X4(aF[mt],  smem_u32(s_NEh + (wm + mt*16 + aRow) * F_LD + kg + aCol));
                    LDSM_X4(alF[mt], smem_u32(s_NEl + (wm + mt*16 + aRow) * F_LD + kg + aCol));
                }
                #pragma unroll
                for (int g = 0; g < 2; g++)
                    LDSM_X4_T(bF[g], smem_u32(s_W + (kl + aRow) * F_LD + wn + g*16 + aCol));
                #pragma unroll
                for (int mt = 0; mt < 2; mt++)
                    #pragma unroll
                    for (int j = 0; j < 4; j++)
                        MMA_F16(facc[mt][j], aF[mt], (&bF[j >> 1][(j & 1) * 2]));
                #pragma unroll
                for (int mt = 0; mt < 2; mt++)
                    #pragma unroll
                    for (int j = 0; j < 4; j++)
                        MMA_F16(facc[mt][j], alF[mt], (&bF[j >> 1][(j & 1) * 2]));
            }
            __syncthreads();
        }
        #pragma unroll
        for (int mt = 0; mt < 2; mt++) {
            int row = wm + mt * 16 + (lane >> 2);
            #pragma unroll
            for (int j = 0; j < 4; j++) {
                int col = wn + j * 8 + (lane & 3) * 2;
                *(float2*)(s_X + row * NH + col) = make_float2(facc[mt][j][0], facc[mt][j][1]);
                *(float2*)(s_X + (row + 8) * NH + col) = make_float2(facc[mt][j][2], facc[mt][j][3]);
            }
        }
    }
    __syncthreads();

    // bias pass + Xh fp16
    {
        int r0 = (tid >> 4) * 4, c0 = (tid & 15) * 8;
        #pragma unroll
        for (int i = 0; i < 4; i++) {
            int l = r0 + i;
            float dl = s_delta[l];
            const float* rp = g_Rproj + s_hr[l] * NH + c0;
            #pragma unroll
            for (int j = 0; j < 8; j++) {
                float x = s_X[l * NH + c0 + j] + s_bias[c0 + j] + s_vdb[c0 + j]
                        + dl * s_vdW[c0 + j] + rp[j];
                s_X[l * NH + c0 + j] = x;
                s_Xh[l * F_LD + c0 + j] = __float2half_rn(x);
            }
        }
    }
    __syncthreads();

    // GEMM2
    {
        float facc[2][4][4];
        #pragma unroll
        for (int i = 0; i < 2; i++)
            #pragma unroll
            for (int j = 0; j < 4; j++)
                { facc[i][j][0]=0.f; facc[i][j][1]=0.f; facc[i][j][2]=0.f; facc[i][j][3]=0.f; }
        for (int c = 0; c < 2; c++) {
            #pragma unroll
            for (int i = 0; i < 8; i++) {
                int idx = tid + i * 256;
                int k = idx >> 5, n = (idx & 31) * 4;
                float4 v = ((const float4*)a_W)[(c * 64 + k) * 32 + (idx & 31)];
                f4_to_h2x2(v, (__half2*)(s_W + k * F_LD + n));
            }
            __syncthreads();
            #pragma unroll
            for (int ks = 0; ks < 4; ks++) {
                int kg = c * 64 + ks * 16, kl = ks * 16;
                uint32_t aF[2][4], bF[2][4];
                #pragma unroll
                for (int mt = 0; mt < 2; mt++)
                    LDSM_X4(aF[mt], smem_u32(s_Xh + (wm + mt*16 + aRow) * F_LD + kg + aCol));
                #pragma unroll
                for (int g = 0; g < 2; g++)
                    LDSM_X4_T(bF[g], smem_u32(s_W + (kl + aRow) * F_LD + wn + g*16 + aCol));
                #pragma unroll
                for (int mt = 0; mt < 2; mt++)
                    #pragma unroll
                    for (int j = 0; j < 4; j++)
                        MMA_F16(facc[mt][j], aF[mt], (&bF[j >> 1][(j & 1) * 2]));
            }
            __syncthreads();
        }
        #pragma unroll
        for (int mt = 0; mt < 2; mt++) {
            int row = wm + mt * 16 + (lane >> 2);
            #pragma unroll
            for (int j = 0; j < 4; j++) {
                int col = wn + j * 8 + (lane & 3) * 2;
                float v0 = 1.f / (1.f + __expf(-(facc[mt][j][0] + s_ab[col])));
                float v1 = 1.f / (1.f + __expf(-(facc[mt][j][1] + s_ab[col + 1])));
                float v2 = 1.f / (1.f + __expf(-(facc[mt][j][2] + s_ab[col])));
                float v3 = 1.f / (1.f + __expf(-(facc[mt][j][3] + s_ab[col + 1])));
                *(float2*)(s_A + row * NH + col) = make_float2(v0, v1);
                *(float2*)(s_A + (row + 8) * NH + col) = make_float2(v2, v3);
            }
        }
    }
    __syncthreads();

    // gated scan
    if (tid < 128) {
        float h = 0.f, cgt = s_cgate[tid];
        for (int l = 0; l < NL; l++) {
            float x = s_X[l * NH + tid];
            float a = s_A[l * NH + tid];
            float m = s_mask[l];
            float hn = a * h + (1.f - a) * x;
            h = m * hn + (1.f - m) * h;
            s_X[l * NH + tid] = h * cgt;
        }
    }
    __syncthreads();

    // attention
    if (tid < 32) {
        float p = 0.f;
        for (int j = tid; j < 128; j += 32) p += s_q[j] * s_attnW[128 + j];
        #pragma unroll
        for (int o = 16; o; o >>= 1) p += __shfl_xor_sync(~0u, p, o);
        if (tid == 0) s_qdot[0] = p + attn_b[0];
    }
    __syncthreads();
    for (int l = warp; l < NL; l += 8) {
        float p = 0.f;
        #pragma unroll
        for (int j = lane; j < 128; j += 32) p += s_X[l * NH + j] * s_attnW[j];
        #pragma unroll
        for (int o = 16; o; o >>= 1) p += __shfl_xor_sync(~0u, p, o);
        if (lane == 0) {
            float sc = tanhf(p + s_qdot[0]);
            s_scores[l] = (s_mask[l] <= 0.f) ? -1e9f : sc;
        }
    }
    __syncthreads();
    if (tid < 32) {
        float v0 = s_scores[tid], v1 = s_scores[tid + 32];
        float mx = fmaxf(v0, v1);
        #pragma unroll
        for (int o = 16; o; o >>= 1) mx = fmaxf(mx, __shfl_xor_sync(~0u, mx, o));
        float e0 = __expf(v0 - mx) * s_mask[tid];
        float e1 = __expf(v1 - mx) * s_mask[tid + 32];
        float s = e0 + e1;
        #pragma unroll
        for (int o = 16; o; o >>= 1) s += __shfl_xor_sync(~0u, s, o);
        s = fmaxf(s, 1e-9f);
        s_attn[tid] = e0 / s;
        s_attn[tid + 32] = e1 / s;
    }
    __syncthreads();
    if (tid < 128) {
        float c = 0.f;
        #pragma unroll 4
        for (int l = 0; l < NL; l++) c += s_X[l * NH + tid] * s_attn[l];
        float P = (s_q[tid] + c) * s_rel[tid];
        g_Ph[b * NH + tid] = __float2half_rn(P);
    }
    // signal completion of this batch row to score consumers
    __syncthreads();
    if (tid == 0) {
        __threadfence();
        atomicAdd(&g_cnt[b >> 7], 1);
    }
}

// ---------------- launch ----------------------------------------------------
extern "C" void kernel_launch(void* const* d_in, const int* in_sizes, int n_in,
                              void* d_out, int out_size) {
    const int*   heads        = (const int*)d_in[0];
    const int*   relations    = (const int*)d_in[1];
    const int*   times        = (const int*)d_in[2];
    const int*   hist_ent     = (const int*)d_in[3];
    const int*   hist_rel     = (const int*)d_in[4];
    const float* hist_delta   = (const float*)d_in[5];
    const float* hist_mask    = (const float*)d_in[6];
    const float* entity_emb   = (const float*)d_in[7];
    const float* relation_emb = (const float*)d_in[8];
    const float* time_emb     = (const float*)d_in[9];
    const float* delta_W      = (const float*)d_in[10];
    const float* delta_b      = (const float*)d_in[11];
    const float* query_W      = (const float*)d_in[12];
    const float* query_b      = (const float*)d_in[13];
    const float* in_W         = (const float*)d_in[14];
    const float* in_b         = (const float*)d_in[15];
    const float* a_W          = (const float*)d_in[16];
    const float* a_b          = (const float*)d_in[17];
    const float* hyper_in_W   = (const float*)d_in[18];
    const float* hyper_in_b   = (const float*)d_in[19];
    const float* hyper_gate_W = (const float*)d_in[20];
    const float* hyper_gate_b = (const float*)d_in[21];
    const float* attn_W       = (const float*)d_in[22];
    const float* attn_b       = (const float*)d_in[23];
    float* out = (float*)d_out;

    cudaFuncSetAttribute(setup_kernel, cudaFuncAttributeMaxDynamicSharedMemorySize, SETUP_SMEM);
    cudaFuncSetAttribute(main_kernel, cudaFuncAttributeMaxDynamicSharedMemorySize, MAIN_SMEM);

    setup_kernel<<<SETUP_GRID, 256, SETUP_SMEM>>>(
        heads, relations, times, entity_emb, relation_emb, time_emb,
        query_W, query_b, in_W, in_b, delta_W, delta_b,
        hyper_in_W, hyper_in_b, hyper_gate_W, hyper_gate_b);
    main_kernel<<<MAIN_GRID, 256, MAIN_SMEM>>>(
        relations, hist_ent, hist_rel, hist_delta, hist_mask,
        entity_emb, relation_emb, in_W, a_W, a_b, attn_W, attn_b, out);
}

// round 17
// speedup vs baseline: 1.1085x; 1.0765x over previous
#include <cuda_runtime.h>
#include <cuda_bf16.h>
#include <cuda_fp16.h>
#include <stdint.h>

#define NB   512
#define NL   64
#define NH   128
#define NENT 200000
#define NREL 500

// ---------------- scratch (__device__ globals; no allocs allowed) ----------
__device__ float g_Rproj[NREL * NH];
__device__ float g_vdW[NH];
__device__ float g_vdb[NH];
__device__ float g_q[NB * NH];
__device__ float g_cgate[NB * NH];
__device__ float g_bias[NB * NH];       // in_b + cond_in (vdb added in front)
__device__ __half g_Ph[NB * NH];
__device__ __half g_Eh[(size_t)NENT * NH];
__device__ __half g_W1h[NH * NH];       // fp16 in_W[0:128]
__device__ __half g_W2h[NH * NH];       // fp16 a_W

// ---------------- shared macros ---------------------------------------------
#define MMA_F16(d, a, b) asm volatile( \
    "mma.sync.aligned.m16n8k16.row.col.f32.f16.f16.f32 " \
    "{%0,%1,%2,%3},{%4,%5,%6,%7},{%8,%9},{%0,%1,%2,%3};" \
    : "+f"(d[0]), "+f"(d[1]), "+f"(d[2]), "+f"(d[3]) \
    : "r"(a[0]), "r"(a[1]), "r"(a[2]), "r"(a[3]), "r"(b[0]), "r"(b[1]))

#define LDSM_X4(r, addr) asm volatile( \
    "ldmatrix.sync.aligned.m8n8.x4.shared.b16 {%0,%1,%2,%3}, [%4];" \
    : "=r"((r)[0]), "=r"((r)[1]), "=r"((r)[2]), "=r"((r)[3]) : "r"(addr))

#define LDSM_X4_T(r, addr) asm volatile( \
    "ldmatrix.sync.aligned.m8n8.x4.trans.shared.b16 {%0,%1,%2,%3}, [%4];" \
    : "=r"((r)[0]), "=r"((r)[1]), "=r"((r)[2]), "=r"((r)[3]) : "r"(addr))

#define CP_ASYNC16(dst, src, srcsz) asm volatile( \
    "cp.async.cg.shared.global [%0], [%1], 16, %2;" \
    :: "r"(dst), "l"(src), "r"(srcsz) : "memory")

__device__ __forceinline__ uint32_t smem_u32(const void* p) {
    return (uint32_t)__cvta_generic_to_shared(p);
}

__device__ __forceinline__ void f4_to_h2x2(float4 v, __half2* dst) {
    dst[0] = __floats2half2_rn(v.x, v.y);
    dst[1] = __floats2half2_rn(v.z, v.w);
}

// ---- setup: qcond (0..7) | prep (8..258) | Wconv (259,260) | convE (261..) -
#define Q_LD 392
#define SETUP_SMEM (64 * Q_LD * 2 + 128 * 136 * 2)   // 84992
#define NCONV_F4 (NENT * NH / 4)                      // 6,400,000
#define NCONV_BLK ((NCONV_F4 + 4095) / 4096)          // 1563
#define SETUP_GRID (8 + 251 + 2 + NCONV_BLK)

__global__ __launch_bounds__(256) void setup_kernel(
    const int* __restrict__ heads, const int* __restrict__ relations,
    const int* __restrict__ times, const float* __restrict__ entity_emb,
    const float* __restrict__ relation_emb, const float* __restrict__ time_emb,
    const float* __restrict__ query_W, const float* __restrict__ query_b,
    const float* __restrict__ in_W, const float* __restrict__ in_b,
    const float* __restrict__ delta_W, const float* __restrict__ delta_b,
    const float* __restrict__ hyper_in_W, const float* __restrict__ hyper_in_b,
    const float* __restrict__ hyper_gate_W, const float* __restrict__ hyper_gate_b,
    const float* __restrict__ a_W)
{
    extern __shared__ char qsm[];
    int tid = threadIdx.x;
    int bid = blockIdx.x;

    if (bid >= 261) {
        // ---- convertE: fp32 E -> fp16 g_Eh ----
        int base = (bid - 261) * 4096 + tid;
        #pragma unroll
        for (int i = 0; i < 16; i++) {
            int idx = base + i * 256;
            if (idx < NCONV_F4) {
                float4 v = ((const float4*)entity_emb)[idx];
                ((__half2*)g_Eh)[2*idx+0] = __floats2half2_rn(v.x, v.y);
                ((__half2*)g_Eh)[2*idx+1] = __floats2half2_rn(v.z, v.w);
            }
        }
        return;
    }

    if (bid >= 259) {
        // ---- weight fp16 conversion: 259 -> in_W[0:128], 260 -> a_W ----
        const float* src = (bid == 259) ? in_W : a_W;
        __half* dst = (bid == 259) ? g_W1h : g_W2h;
        #pragma unroll
        for (int i = 0; i < 16; i++) {
            int idx = tid + i * 256;              // 0..4095 float4
            float4 v = ((const float4*)src)[idx];
            f4_to_h2x2(v, (__half2*)(dst + idx * 4));
        }
        return;
    }

    if (bid >= 8) {
        // ---- prep: Rproj (2 rels/blk) or vdW/vdb ----
        int pb = bid - 8;
        int j = tid & 127;
        if (pb < 250) {
            float* sr = (float*)qsm;
            int half = tid >> 7;
            int r = pb * 2 + half;
            sr[half * NH + j] = relation_emb[r * NH + j];
            __syncthreads();
            float a0 = 0.f, a1 = 0.f;
            #pragma unroll 8
            for (int i = 0; i < NH; i += 2) {
                a0 += sr[half * NH + i]   * in_W[(NH + i) * NH + j];
                a1 += sr[half * NH + i+1] * in_W[(NH + i + 1) * NH + j];
            }
            g_Rproj[r * NH + j] = a0 + a1;
        } else {
            const float* v = (tid < 128) ? delta_W : delta_b;
            float a0 = 0.f, a1 = 0.f;
            #pragma unroll 8
            for (int t = 0; t < 128; t += 2) {
                a0 += v[t]   * in_W[(256 + t) * NH + j];
                a1 += v[t+1] * in_W[(256 + t + 1) * NH + j];
            }
            if (tid < 128) g_vdW[j] = a0 + a1; else g_vdb[j] = a0 + a1;
        }
        return;
    }

    // ---- qcond: q / cond_in / cond_gate for 64 batch rows ----
    __half* sA = (__half*)qsm;
    __half* sW = (__half*)(qsm + 64 * Q_LD * 2);
    int warp = tid >> 5, lane = tid & 31;
    int b0 = bid * 64;

    for (int l = warp; l < 64; l += 8) {
        int b = b0 + l;
        float4 v0 = ((const float4*)(entity_emb + (size_t)heads[b] * NH))[lane];
        float4 v1 = ((const float4*)(relation_emb + relations[b] * NH))[lane];
        float4 v2 = ((const float4*)(time_emb + times[b] * NH))[lane];
        f4_to_h2x2(v0, (__half2*)(sA + l * Q_LD + lane * 4));
        f4_to_h2x2(v1, (__half2*)(sA + l * Q_LD + 128 + lane * 4));
        f4_to_h2x2(v2, (__half2*)(sA + l * Q_LD + 256 + lane * 4));
    }
    __syncthreads();

    int wm = (warp >> 2) * 32, wn = (warp & 3) * 32;
    int aRow = lane & 15, aCol = (lane >> 4) * 8;

    float qa[2][4][4];
    #pragma unroll
    for (int i = 0; i < 2; i++)
        #pragma unroll
        for (int j = 0; j < 4; j++)
            { qa[i][j][0]=0.f; qa[i][j][1]=0.f; qa[i][j][2]=0.f; qa[i][j][3]=0.f; }
    for (int c = 0; c < 3; c++) {
        #pragma unroll
        for (int i = 0; i < 16; i++) {
            int idx = tid + i * 256;
            int k = idx >> 5, n = (idx & 31) * 4;
            float4 v = ((const float4*)(query_W + c * 128 * NH))[idx];
            f4_to_h2x2(v, (__half2*)(sW + k * 136 + n));
        }
        __syncthreads();
        #pragma unroll
        for (int ks = 0; ks < 8; ks++) {
            int kg = c * 128 + ks * 16, kl = ks * 16;
            uint32_t aF[2][4], bF[2][4];
            #pragma unroll
            for (int mt = 0; mt < 2; mt++)
                LDSM_X4(aF[mt], smem_u32(sA + (wm + mt*16 + aRow) * Q_LD + kg + aCol));
            #pragma unroll
            for (int g = 0; g < 2; g++)
                LDSM_X4_T(bF[g], smem_u32(sW + (kl + aRow) * 136 + wn + g*16 + aCol));
            #pragma unroll
            for (int mt = 0; mt < 2; mt++)
                #pragma unroll
                for (int j = 0; j < 4; j++)
                    MMA_F16(qa[mt][j], aF[mt], (&bF[j >> 1][(j & 1) * 2]));
        }
        __syncthreads();
    }
    #pragma unroll
    for (int mt = 0; mt < 2; mt++) {
        int row = wm + mt * 16 + (lane >> 2);
        #pragma unroll
        for (int j = 0; j < 4; j++) {
            int col = wn + j * 8 + (lane & 3) * 2;
            g_q[(b0 + row) * NH + col]     = qa[mt][j][0] + query_b[col];
            g_q[(b0 + row) * NH + col + 1] = qa[mt][j][1] + query_b[col + 1];
            g_q[(b0 + row + 8) * NH + col]     = qa[mt][j][2] + query_b[col];
            g_q[(b0 + row + 8) * NH + col + 1] = qa[mt][j][3] + query_b[col + 1];
        }
    }

    float ci[2][4][4], cg[2][4][4];
    #pragma unroll
    for (int i = 0; i < 2; i++)
        #pragma unroll
        for (int j = 0; j < 4; j++) {
            ci[i][j][0]=0.f; ci[i][j][1]=0.f; ci[i][j][2]=0.f; ci[i][j][3]=0.f;
            cg[i][j][0]=0.f; cg[i][j][1]=0.f; cg[i][j][2]=0.f; cg[i][j][3]=0.f;
        }
    for (int pass = 0; pass < 2; pass++) {
        const float* W = pass ? hyper_gate_W : hyper_in_W;
        #pragma unroll
        for (int i = 0; i < 16; i++) {
            int idx = tid + i * 256;
            int k = idx >> 5, n = (idx & 31) * 4;
            float4 v = ((const float4*)W)[idx];
            f4_to_h2x2(v, (__half2*)(sW + k * 136 + n));
        }
        __syncthreads();
        #pragma unroll
        for (int ks = 0; ks < 8; ks++) {
            int kl = ks * 16;
            uint32_t aF[2][4], bF[2][4];
            #pragma unroll
            for (int mt = 0; mt < 2; mt++)
                LDSM_X4(aF[mt], smem_u32(sA + (wm + mt*16 + aRow) * Q_LD + 128 + kl + aCol));
            #pragma unroll
            for (int g = 0; g < 2; g++)
                LDSM_X4_T(bF[g], smem_u32(sW + (kl + aRow) * 136 + wn + g*16 + aCol));
            if (pass == 0) {
                #pragma unroll
                for (int mt = 0; mt < 2; mt++)
                    #pragma unroll
                    for (int j = 0; j < 4; j++)
                        MMA_F16(ci[mt][j], aF[mt], (&bF[j >> 1][(j & 1) * 2]));
            } else {
                #pragma unroll
                for (int mt = 0; mt < 2; mt++)
                    #pragma unroll
                    for (int j = 0; j < 4; j++)
                        MMA_F16(cg[mt][j], aF[mt], (&bF[j >> 1][(j & 1) * 2]));
            }
        }
        __syncthreads();
    }
    #pragma unroll
    for (int mt = 0; mt < 2; mt++) {
        int row = wm + mt * 16 + (lane >> 2);
        #pragma unroll
        for (int j = 0; j < 4; j++) {
            int col = wn + j * 8 + (lane & 3) * 2;
            #pragma unroll
            for (int h = 0; h < 2; h++) {
                int rr = b0 + row + h * 8;
                float i0 = ci[mt][j][h*2], i1 = ci[mt][j][h*2+1];
                float t0 = cg[mt][j][h*2], t1 = cg[mt][j][h*2+1];
                g_bias[rr * NH + col]     = in_b[col] + i0;
                g_bias[rr * NH + col + 1] = in_b[col+1] + i1;
                g_cgate[rr * NH + col]     = 1.f / (1.f + __expf(-(t0 + hyper_gate_b[col])));
                g_cgate[rr * NH + col + 1] = 1.f / (1.f + __expf(-(t1 + hyper_gate_b[col+1])));
            }
        }
    }
}

// ---------------- front: one CTA per batch row, 2 CTAs/SM -------------------
// smem: s_X 0..32768 | s_NEh 32768..50176 | s_W0 50176..67584 |
//       s_W1 67584..84992 | s_Xh 84992..102400 | misc 102400..109056
// s_A (fp32 32KB) aliases W0+W1 (50176..82944) after GEMM2 W reads complete.
#define F_LD 136
#define FRONT_SMEM 109056
#define SW0 50176
#define SW1 67584
__global__ __launch_bounds__(256, 2) void front_kernel(
    const int* __restrict__ relations,
    const int* __restrict__ hist_ent, const int* __restrict__ hist_rel,
    const float* __restrict__ hist_delta, const float* __restrict__ hist_mask,
    const float* __restrict__ entity_emb, const float* __restrict__ relation_emb,
    const float* __restrict__ a_b,
    const float* __restrict__ attn_W, const float* __restrict__ attn_b)
{
    extern __shared__ char fsm[];
    uint32_t sb = smem_u32(fsm);
    float*  s_X   = (float*)fsm;
    __half* s_NEh = (__half*)(fsm + 32768);
    float*  s_A   = (float*)(fsm + SW0);         // aliases W bufs after GEMM2
    __half* s_Xh  = (__half*)(fsm + 84992);
    float*  s_misc = (float*)(fsm + 102400);
    float* s_rel    = s_misc;
    float* s_q      = s_misc + 128;
    float* s_cgate  = s_misc + 256;
    float* s_bias   = s_misc + 384;
    float* s_vdW    = s_misc + 512;
    float* s_attnW  = s_misc + 640;
    float* s_vdb    = s_misc + 896;
    float* s_scores = s_misc + 1152;
    float* s_attn   = s_misc + 1216;
    float* s_delta  = s_misc + 1280;
    float* s_mask   = s_misc + 1344;
    int*   s_hr     = (int*)(s_misc + 1408);
    float* s_qdot   = s_misc + 1472;
    float* s_ab     = s_misc + 1480;

    int b = blockIdx.x, tid = threadIdx.x;
    int warp = tid >> 5, lane = tid & 31;

    // W staging via cp.async (fp16 source, no conversion)
    auto fillW = [&](const __half* src, int chunk, uint32_t bufoff) {
        #pragma unroll
        for (int i = 0; i < 4; i++) {
            int idx = tid + i * 256;          // 0..1023 (64 rows x 16 pieces)
            int k = idx >> 4, n16 = idx & 15;
            CP_ASYNC16(sb + bufoff + (uint32_t)(k * (F_LD * 2) + n16 * 16),
                       src + (size_t)(chunk * 64 + k) * NH + n16 * 8, 16u);
        }
    };

    fillW(g_W1h, 0, SW0);
    asm volatile("cp.async.commit_group;" ::: "memory");   // G0
    fillW(g_W1h, 1, SW1);
    asm volatile("cp.async.commit_group;" ::: "memory");   // G1

    if (tid < 128) {
        s_rel[tid]   = relation_emb[relations[b] * NH + tid];
        s_q[tid]     = g_q[b * NH + tid];
        s_cgate[tid] = g_cgate[b * NH + tid];
        s_bias[tid]  = g_bias[b * NH + tid];
        s_vdW[tid]   = g_vdW[tid];
        s_vdb[tid]   = g_vdb[tid];
        s_ab[tid]    = a_b[tid];
    } else {
        int j = tid - 128;
        s_attnW[j]       = attn_W[j];
        s_attnW[128 + j] = attn_W[128 + j];
    }
    if (tid < 64) {
        s_delta[tid] = hist_delta[b * NL + tid];
        s_mask[tid]  = hist_mask[b * NL + tid];
        s_hr[tid]    = hist_rel[b * NL + tid];
    }

    // gather NE -> fp16 (1-term)
    for (int l = warp; l < NL; l += 8) {
        size_t e = (size_t)hist_ent[b * NL + l];
        float4 v = ((const float4*)(entity_emb + e * NH))[lane];
        f4_to_h2x2(v, (__half2*)(s_NEh + l * F_LD + lane * 4));
    }

    int wm = (warp >> 2) * 32, wn = (warp & 3) * 32;
    int aRow = lane & 15, aCol = (lane >> 4) * 8;

    // ---- GEMM1: X = NE @ W1 ----
    float facc[2][4][4];
    #pragma unroll
    for (int i = 0; i < 2; i++)
        #pragma unroll
        for (int j = 0; j < 4; j++)
            { facc[i][j][0]=0.f; facc[i][j][1]=0.f; facc[i][j][2]=0.f; facc[i][j][3]=0.f; }

    // chunk 0
    asm volatile("cp.async.wait_group 1;" ::: "memory");    // G0 done
    __syncthreads();                                         // NE + W0 visible
    #pragma unroll
    for (int ks = 0; ks < 4; ks++) {
        int kg = ks * 16;
        uint32_t aF[2][4], bF[2][4];
        #pragma unroll
        for (int mt = 0; mt < 2; mt++)
            LDSM_X4(aF[mt], smem_u32(s_NEh + (wm + mt*16 + aRow) * F_LD + kg + aCol));
        #pragma unroll
        for (int g = 0; g < 2; g++)
            LDSM_X4_T(bF[g], sb + SW0 + (uint32_t)((kg + aRow) * (F_LD*2) + (wn + g*16 + aCol) * 2));
        #pragma unroll
        for (int mt = 0; mt < 2; mt++)
            #pragma unroll
            for (int j = 0; j < 4; j++)
                MMA_F16(facc[mt][j], aF[mt], (&bF[j >> 1][(j & 1) * 2]));
    }
    __syncthreads();                                         // all done reading W0
    fillW(g_W2h, 0, SW0);
    asm volatile("cp.async.commit_group;" ::: "memory");     // G2

    // chunk 1
    asm volatile("cp.async.wait_group 1;" ::: "memory");     // G1 done
    __syncthreads();
    #pragma unroll
    for (int ks = 0; ks < 4; ks++) {
        int kg = 64 + ks * 16, kl = ks * 16;
        uint32_t aF[2][4], bF[2][4];
        #pragma unroll
        for (int mt = 0; mt < 2; mt++)
            LDSM_X4(aF[mt], smem_u32(s_NEh + (wm + mt*16 + aRow) * F_LD + kg + aCol));
        #pragma unroll
        for (int g = 0; g < 2; g++)
            LDSM_X4_T(bF[g], sb + SW1 + (uint32_t)((kl + aRow) * (F_LD*2) + (wn + g*16 + aCol) * 2));
        #pragma unroll
        for (int mt = 0; mt < 2; mt++)
            #pragma unroll
            for (int j = 0; j < 4; j++)
                MMA_F16(facc[mt][j], aF[mt], (&bF[j >> 1][(j & 1) * 2]));
    }
    // GEMM1 epilogue -> s_X (no overlap with W bufs)
    #pragma unroll
    for (int mt = 0; mt < 2; mt++) {
        int row = wm + mt * 16 + (lane >> 2);
        #pragma unroll
        for (int j = 0; j < 4; j++) {
            int col = wn + j * 8 + (lane & 3) * 2;
            *(float2*)(s_X + row * NH + col) = make_float2(facc[mt][j][0], facc[mt][j][1]);
            *(float2*)(s_X + (row + 8) * NH + col) = make_float2(facc[mt][j][2], facc[mt][j][3]);
        }
    }
    __syncthreads();                                         // W1 reads + X writes done
    fillW(g_W2h, 1, SW1);
    asm volatile("cp.async.commit_group;" ::: "memory");     // G3

    // bias pass + Xh fp16
    {
        int r0 = (tid >> 4) * 4, c0 = (tid & 15) * 8;
        #pragma unroll
        for (int i = 0; i < 4; i++) {
            int l = r0 + i;
            float dl = s_delta[l];
            const float* rp = g_Rproj + s_hr[l] * NH + c0;
            #pragma unroll
            for (int j = 0; j < 8; j++) {
                float x = s_X[l * NH + c0 + j] + s_bias[c0 + j] + s_vdb[c0 + j]
                        + dl * s_vdW[c0 + j] + rp[j];
                s_X[l * NH + c0 + j] = x;
                s_Xh[l * F_LD + c0 + j] = __float2half_rn(x);
            }
        }
    }

    // ---- GEMM2: A = sigmoid(Xh @ W2 + a_b) ----
    #pragma unroll
    for (int i = 0; i < 2; i++)
        #pragma unroll
        for (int j = 0; j < 4; j++)
            { facc[i][j][0]=0.f; facc[i][j][1]=0.f; facc[i][j][2]=0.f; facc[i][j][3]=0.f; }

    asm volatile("cp.async.wait_group 1;" ::: "memory");     // G2 done
    __syncthreads();                                         // Xh + W0(G2) visible
    #pragma unroll
    for (int ks = 0; ks < 4; ks++) {
        int kg = ks * 16;
        uint32_t aF[2][4], bF[2][4];
        #pragma unroll
        for (int mt = 0; mt < 2; mt++)
            LDSM_X4(aF[mt], smem_u32(s_Xh + (wm + mt*16 + aRow) * F_LD + kg + aCol));
        #pragma unroll
        for (int g = 0; g < 2; g++)
            LDSM_X4_T(bF[g], sb + SW0 + (uint32_t)((kg + aRow) * (F_LD*2) + (wn + g*16 + aCol) * 2));
        #pragma unroll
        for (int mt = 0; mt < 2; mt++)
            #pragma unroll
            for (int j = 0; j < 4; j++)
                MMA_F16(facc[mt][j], aF[mt], (&bF[j >> 1][(j & 1) * 2]));
    }
    asm volatile("cp.async.wait_group 0;" ::: "memory");     // G3 done
    __syncthreads();
    #pragma unroll
    for (int ks = 0; ks < 4; ks++) {
        int kg = 64 + ks * 16, kl = ks * 16;
        uint32_t aF[2][4], bF[2][4];
        #pragma unroll
        for (int mt = 0; mt < 2; mt++)
            LDSM_X4(aF[mt], smem_u32(s_Xh + (wm + mt*16 + aRow) * F_LD + kg + aCol));
        #pragma unroll
        for (int g = 0; g < 2; g++)
            LDSM_X4_T(bF[g], sb + SW1 + (uint32_t)((kl + aRow) * (F_LD*2) + (wn + g*16 + aCol) * 2));
        #pragma unroll
        for (int mt = 0; mt < 2; mt++)
            #pragma unroll
            for (int j = 0; j < 4; j++)
                MMA_F16(facc[mt][j], aF[mt], (&bF[j >> 1][(j & 1) * 2]));
    }
    __syncthreads();                                         // all W reads done (A aliases W)
    #pragma unroll
    for (int mt = 0; mt < 2; mt++) {
        int row = wm + mt * 16 + (lane >> 2);
        #pragma unroll
        for (int j = 0; j < 4; j++) {
            int col = wn + j * 8 + (lane & 3) * 2;
            float v0 = 1.f / (1.f + __expf(-(facc[mt][j][0] + s_ab[col])));
            float v1 = 1.f / (1.f + __expf(-(facc[mt][j][1] + s_ab[col + 1])));
            float v2 = 1.f / (1.f + __expf(-(facc[mt][j][2] + s_ab[col])));
            float v3 = 1.f / (1.f + __expf(-(facc[mt][j][3] + s_ab[col + 1])));
            *(float2*)(s_A + row * NH + col) = make_float2(v0, v1);
            *(float2*)(s_A + (row + 8) * NH + col) = make_float2(v2, v3);
        }
    }
    __syncthreads();

    // gated scan
    if (tid < 128) {
        float h = 0.f, cgt = s_cgate[tid];
        for (int l = 0; l < NL; l++) {
            float x = s_X[l * NH + tid];
            float a = s_A[l * NH + tid];
            float m = s_mask[l];
            float hn = a * h + (1.f - a) * x;
            h = m * hn + (1.f - m) * h;
            s_X[l * NH + tid] = h * cgt;
        }
    }
    __syncthreads();

    // attention
    if (tid < 32) {
        float p = 0.f;
        for (int j = tid; j < 128; j += 32) p += s_q[j] * s_attnW[128 + j];
        #pragma unroll
        for (int o = 16; o; o >>= 1) p += __shfl_xor_sync(~0u, p, o);
        if (tid == 0) s_qdot[0] = p + attn_b[0];
    }
    __syncthreads();
    for (int l = warp; l < NL; l += 8) {
        float p = 0.f;
        #pragma unroll
        for (int j = lane; j < 128; j += 32) p += s_X[l * NH + j] * s_attnW[j];
        #pragma unroll
        for (int o = 16; o; o >>= 1) p += __shfl_xor_sync(~0u, p, o);
        if (lane == 0) {
            float sc = tanhf(p + s_qdot[0]);
            s_scores[l] = (s_mask[l] <= 0.f) ? -1e9f : sc;
        }
    }
    __syncthreads();
    if (tid < 32) {
        float v0 = s_scores[tid], v1 = s_scores[tid + 32];
        float mx = fmaxf(v0, v1);
        #pragma unroll
        for (int o = 16; o; o >>= 1) mx = fmaxf(mx, __shfl_xor_sync(~0u, mx, o));
        float e0 = __expf(v0 - mx) * s_mask[tid];
        float e1 = __expf(v1 - mx) * s_mask[tid + 32];
        float s = e0 + e1;
        #pragma unroll
        for (int o = 16; o; o >>= 1) s += __shfl_xor_sync(~0u, s, o);
        s = fmaxf(s, 1e-9f);
        s_attn[tid] = e0 / s;
        s_attn[tid + 32] = e1 / s;
    }
    __syncthreads();
    if (tid < 128) {
        float c = 0.f;
        #pragma unroll 4
        for (int l = 0; l < NL; l++) c += s_X[l * NH + tid] * s_attn[l];
        float P = (s_q[tid] + c) * s_rel[tid];
        g_Ph[b * NH + tid] = __float2half_rn(P);
    }
}

// ---------------- score: fp16 GEMM, 128m x 128n, 2 CTAs/SM (proven) --------
#define ALD 136
#define SLD 72
#define SB_OFF 34816
#define BSTAGE 18432
#define NSTAGES 4
#define SCORE_SMEM (SB_OFF + NSTAGES * BSTAGE)   // 108544
#define NT128 ((NENT + 127) / 128)               // 1563
#define NSTRIDE 74

__global__ __launch_bounds__(256, 2) void score_kernel(float* __restrict__ out) {
    extern __shared__ char smem[];
    uint32_t sbase = smem_u32(smem);
    int tid = threadIdx.x, warp = tid >> 5, lane = tid & 31;
    int m0 = (blockIdx.x & 3) * 128;
    int nstart = blockIdx.x >> 2;

    int wm = (warp >> 2) * 64;
    int wn = (warp & 3) * 32;
    int aRow = lane & 15, aCol = (lane >> 4) * 8;
    int bRow = ((lane >> 4) << 3) + (lane & 7);
    int bCol = ((lane >> 3) & 1) * 8;
    int arow = lane >> 2, acol = (lane & 3) * 2;

    #pragma unroll
    for (int i = 0; i < 8; i++) {
        int idx = tid + i * 256;
        int r = idx >> 4, c = (idx & 15) * 8;
        *(uint4*)(smem + r * (ALD * 2) + c * 2) =
            *(const uint4*)(g_Ph + (size_t)(m0 + r) * NH + c);
    }

    int ntiles = 0;
    for (int t = nstart; t < NT128; t += NSTRIDE) ntiles++;
    int steps = ntiles * 2;
    if (steps == 0) return;

    auto fillB = [&](int s) {
        int stage = s & 3;
        int n0 = (nstart + (s >> 1) * NSTRIDE) * 128;
        int kc = (s & 1) * 64;
        uint32_t bh = sbase + SB_OFF + stage * BSTAGE;
        #pragma unroll
        for (int i = 0; i < 4; i++) {
            int idx = tid + i * 256;
            int r = idx >> 3, c = (idx & 7) * 8;
            int er = n0 + r;
            uint32_t srcsz = (er < NENT) ? 16u : 0u;
            size_t go = (size_t)er * NH + kc + c;
            uint32_t so = (uint32_t)(r * (SLD * 2) + c * 2);
            CP_ASYNC16(bh + so, g_Eh + (srcsz ? go : 0), srcsz);
        }
    };

    fillB(0); asm volatile("cp.async.commit_group;" ::: "memory");
    if (steps > 1) { fillB(1); asm volatile("cp.async.commit_group;" ::: "memory"); }
    if (steps > 2) { fillB(2); asm volatile("cp.async.commit_group;" ::: "memory"); }

    float acc[4][4][4];
    #pragma unroll
    for (int i = 0; i < 4; i++)
        #pragma unroll
        for (int j = 0; j < 4; j++)
            { acc[i][j][0]=0.f; acc[i][j][1]=0.f; acc[i][j][2]=0.f; acc[i][j][3]=0.f; }

    for (int s = 0; s < steps; s++) {
        int rem = steps - 1 - s;
        if (rem >= 2)      asm volatile("cp.async.wait_group 2;" ::: "memory");
        else if (rem == 1) asm volatile("cp.async.wait_group 1;" ::: "memory");
        else               asm volatile("cp.async.wait_group 0;" ::: "memory");
        __syncthreads();

        if (s + 3 < steps) {
            fillB(s + 3);
            asm volatile("cp.async.commit_group;" ::: "memory");
        }

        int stage = s & 3;
        int kA = (s & 1) * 64;
        const char* bhp = smem + SB_OFF + stage * BSTAGE;

        #pragma unroll
        for (int ks = 0; ks < 4; ks++) {
            int k = ks * 16;
            uint32_t aH[4][4], bH[2][4];
            #pragma unroll
            for (int mt = 0; mt < 4; mt++)
                LDSM_X4(aH[mt], sbase +
                        (wm + mt * 16 + aRow) * (ALD * 2) + (kA + k + aCol) * 2);
            #pragma unroll
            for (int p = 0; p < 2; p++)
                LDSM_X4(bH[p], smem_u32(bhp + (wn + p * 16 + bRow) * (SLD * 2) + (k + bCol) * 2));
            #pragma unroll
            for (int mt = 0; mt < 4; mt++)
                #pragma unroll
                for (int nt = 0; nt < 4; nt++)
                    MMA_F16(acc[mt][nt], aH[mt], (&bH[nt >> 1][(nt & 1) * 2]));
        }

        if (s & 1) {
            int n0 = (nstart + (s >> 1) * NSTRIDE) * 128;
            #pragma unroll
            for (int mt = 0; mt < 4; mt++) {
                int row = m0 + wm + mt * 16 + arow;
                #pragma unroll
                for (int nt = 0; nt < 4; nt++) {
                    int col = n0 + wn + nt * 8 + acol;
                    if (col < NENT) {
                        __stcs((float2*)(out + (size_t)row * NENT + col),
                               make_float2(acc[mt][nt][0], acc[mt][nt][1]));
                        __stcs((float2*)(out + (size_t)(row + 8) * NENT + col),
                               make_float2(acc[mt][nt][2], acc[mt][nt][3]));
                    }
                }
            }
            #pragma unroll
            for (int i = 0; i < 4; i++)
                #pragma unroll
                for (int j = 0; j < 4; j++)
                    { acc[i][j][0]=0.f; acc[i][j][1]=0.f; acc[i][j][2]=0.f; acc[i][j][3]=0.f; }
        }
    }
}

// ---------------- launch ----------------------------------------------------
extern "C" void kernel_launch(void* const* d_in, const int* in_sizes, int n_in,
                              void* d_out, int out_size) {
    const int*   heads        = (const int*)d_in[0];
    const int*   relations    = (const int*)d_in[1];
    const int*   times        = (const int*)d_in[2];
    const int*   hist_ent     = (const int*)d_in[3];
    const int*   hist_rel     = (const int*)d_in[4];
    const float* hist_delta   = (const float*)d_in[5];
    const float* hist_mask    = (const float*)d_in[6];
    const float* entity_emb   = (const float*)d_in[7];
    const float* relation_emb = (const float*)d_in[8];
    const float* time_emb     = (const float*)d_in[9];
    const float* delta_W      = (const float*)d_in[10];
    const float* delta_b      = (const float*)d_in[11];
    const float* query_W      = (const float*)d_in[12];
    const float* query_b      = (const float*)d_in[13];
    const float* in_W         = (const float*)d_in[14];
    const float* in_b         = (const float*)d_in[15];
    const float* a_W          = (const float*)d_in[16];
    const float* a_b          = (const float*)d_in[17];
    const float* hyper_in_W   = (const float*)d_in[18];
    const float* hyper_in_b   = (const float*)d_in[19];
    const float* hyper_gate_W = (const float*)d_in[20];
    const float* hyper_gate_b = (const float*)d_in[21];
    const float* attn_W       = (const float*)d_in[22];
    const float* attn_b       = (const float*)d_in[23];
    float* out = (float*)d_out;

    cudaFuncSetAttribute(setup_kernel, cudaFuncAttributeMaxDynamicSharedMemorySize, SETUP_SMEM);
    cudaFuncSetAttribute(front_kernel, cudaFuncAttributeMaxDynamicSharedMemorySize, FRONT_SMEM);
    cudaFuncSetAttribute(score_kernel, cudaFuncAttributeMaxDynamicSharedMemorySize, SCORE_SMEM);

    setup_kernel<<<SETUP_GRID, 256, SETUP_SMEM>>>(
        heads, relations, times, entity_emb, relation_emb, time_emb,
        query_W, query_b, in_W, in_b, delta_W, delta_b,
        hyper_in_W, hyper_in_b, hyper_gate_W, hyper_gate_b, a_W);
    front_kernel<<<NB, 256, FRONT_SMEM>>>(
        relations, hist_ent, hist_rel, hist_delta, hist_mask,
        entity_emb, relation_emb, a_b, attn_W, attn_b);
    score_kernel<<<296, 256, SCORE_SMEM>>>(out);
}